// round 6
// baseline (speedup 1.0000x reference)
#include <cuda_runtime.h>

constexpr int NMAX  = 100000;
constexpr int D_IN  = 16;
constexpr int D_HID = 32;
constexpr int D_OUT = 16;

// Scratch (__device__ globals; allocation-free rule). Zero-initialized at load.
__device__ alignas(16) float g_pre [NMAX * D_IN];   // emb[x[v]] * dinv[v]
__device__ alignas(16) float g_agg1[NMAX * D_IN];   // self + Sum over in-edges
__device__ alignas(16) float g_hs2 [NMAX * D_OUT];  // (relu(conv1)@W2) * dinv
__device__ alignas(16) float g_agg2[NMAX * D_OUT];  // self + Sum over in-edges
__device__ float g_dinv[NMAX];
__device__ int   g_deg [NMAX];   // 0 at entry (static init / reset by k_pre)

// ---------------------------------------------------------------------------
// K1: degree histogram over real edges (self-loop folded as +1 in k_pre).
__global__ void k_deg(const int* __restrict__ dst, int E) {
    int i = blockIdx.x * blockDim.x + threadIdx.x;
    int e4 = i * 4;
    if (e4 + 3 < E) {
        int4 d = *reinterpret_cast<const int4*>(dst + e4);
        atomicAdd(&g_deg[d.x], 1); atomicAdd(&g_deg[d.y], 1);
        atomicAdd(&g_deg[d.z], 1); atomicAdd(&g_deg[d.w], 1);
    } else {
        for (int e = e4; e < E && e >= 0; e++) atomicAdd(&g_deg[dst[e]], 1);
    }
}

// K2: 4 threads per node (one float4 chunk each): dinv; pre = emb[x[v]]*dinv;
//     agg1 = pre (self-loop seed); reset deg. Node's 4 threads share a warp
//     and are convergent at the load, so read-before-lane0-reset is race-free.
__global__ void k_pre(const int* __restrict__ x, const float* __restrict__ emb,
                      int n) {
    int t = blockIdx.x * blockDim.x + threadIdx.x;
    int v = t >> 2, q = t & 3;
    if (v >= n) return;
    int d = g_deg[v];
    float dinv = rsqrtf((float)(d + 1));
    if (q == 0) { g_deg[v] = 0; g_dinv[v] = dinv; }
    int xr = __ldg(&x[v]);
    float4 e = reinterpret_cast<const float4*>(emb)[(size_t)xr * 4 + q];
    float4 p = make_float4(e.x * dinv, e.y * dinv, e.z * dinv, e.w * dinv);
    reinterpret_cast<float4*>(g_pre )[(size_t)v * 4 + q] = p;
    reinterpret_cast<float4*>(g_agg1)[(size_t)v * 4 + q] = p;
}

// K3/K5: edge scatter in 16-dim space: 4 threads per edge, red.v4 per thread.
template <int LAYER>
__global__ void k_scatter(const int* __restrict__ src, const int* __restrict__ dst,
                          int E) {
    const float* in  = (LAYER == 1) ? g_pre  : g_hs2;
    float*       out = (LAYER == 1) ? g_agg1 : g_agg2;

    long long t = (long long)blockIdx.x * blockDim.x + threadIdx.x;
    int e = (int)(t >> 2);
    if (e >= E) return;
    int c = (int)t & 3;

    int s = __ldg(&src[e]);
    int d = __ldg(&dst[e]);

    float4 v = *reinterpret_cast<const float4*>(in + ((size_t)s << 4) + c * 4);
    float* p = out + ((size_t)d << 4) + c * 4;
    asm volatile("red.global.add.v4.f32 [%0], {%1,%2,%3,%4};"
                 :: "l"(p), "f"(v.x), "f"(v.y), "f"(v.z), "f"(v.w) : "memory");
}

// K4: warp per node. a = agg1*dinv (lanes 0-15); lane j: r_j = relu(a@W1+b1)_j;
//     h_{j&15} = dinv*(r@W2) via half-split + xor-combine; seed agg2 = hs2 = h.
__global__ void k_mid(const float* __restrict__ W1, const float* __restrict__ b1,
                      const float* __restrict__ W2, int n) {
    __shared__ float W1s[D_IN * D_HID];
    __shared__ float W2s[D_HID * D_OUT];
    __shared__ float b1s[D_HID];
    for (int t = threadIdx.x; t < D_IN * D_HID; t += blockDim.x) W1s[t] = W1[t];
    for (int t = threadIdx.x; t < D_HID * D_OUT; t += blockDim.x) W2s[t] = W2[t];
    if (threadIdx.x < D_HID) b1s[threadIdx.x] = b1[threadIdx.x];
    __syncthreads();

    int gw = (blockIdx.x * blockDim.x + threadIdx.x) >> 5;
    if (gw >= n) return;
    int v = gw;
    int lane = threadIdx.x & 31;

    float dinv = g_dinv[v];
    float a = 0.f;
    if (lane < D_IN) a = g_agg1[(size_t)v * D_IN + lane] * dinv;

    // r_j for j = lane (all 32 columns of W1).
    float r = b1s[lane];
#pragma unroll
    for (int k = 0; k < D_IN; k++)
        r = fmaf(__shfl_sync(~0u, a, k), W1s[k * D_HID + lane], r);
    r = fmaxf(r, 0.f);

    // h_j, j = lane&15; lanes 0-15 sum k=0..15, lanes 16-31 sum k=16..31.
    int half = lane >> 4;
    int j = lane & 15;
    float h = 0.f;
#pragma unroll
    for (int k = 0; k < 16; k++) {
        int kk = half * 16 + k;
        h = fmaf(__shfl_sync(~0u, r, kk), W2s[kk * D_OUT + j], h);
    }
    h += __shfl_xor_sync(~0u, h, 16);
    h *= dinv;
    if (lane < D_OUT) {
        g_hs2 [(size_t)v * D_OUT + lane] = h;
        g_agg2[(size_t)v * D_OUT + lane] = h;
    }
}

// K6: 4 threads per node: out = agg2*dinv + b2.
__global__ void k_post(const float* __restrict__ b2, float* __restrict__ out, int n) {
    int t = blockIdx.x * blockDim.x + threadIdx.x;
    int v = t >> 2, q = t & 3;
    if (v >= n) return;
    float dinv = g_dinv[v];
    float4 a = reinterpret_cast<const float4*>(g_agg2)[(size_t)v * 4 + q];
    float4 bb = __ldg(reinterpret_cast<const float4*>(b2) + q);
    reinterpret_cast<float4*>(out)[(size_t)v * 4 + q] =
        make_float4(dinv * a.x + bb.x, dinv * a.y + bb.y,
                    dinv * a.z + bb.z, dinv * a.w + bb.w);
}

extern "C" void kernel_launch(void* const* d_in, const int* in_sizes, int n_in,
                              void* d_out, int out_size) {
    const int*   x   = (const int*)  d_in[0];
    const int*   ei  = (const int*)  d_in[1];   // [2, E]: src then dst
    const float* emb = (const float*)d_in[2];
    const float* W1  = (const float*)d_in[3];
    const float* b1  = (const float*)d_in[4];
    const float* W2  = (const float*)d_in[5];
    const float* b2  = (const float*)d_in[6];
    float* out = (float*)d_out;

    int n = in_sizes[0];
    int E = in_sizes[1] / 2;
    const int* src = ei;
    const int* dst = ei + E;

    const int B = 256;
    long long et = (long long)E * 4;
    int nb_edge  = (int)((et + B - 1) / B);
    int nb_node4 = (n * 4 + B - 1) / B;
    int nb_node32 = (n * 32 + B - 1) / B;

    k_deg       <<<(E / 4 + B - 1) / B + 1, B>>>(dst, E);
    k_pre       <<<nb_node4, B>>>(x, emb, n);
    k_scatter<1><<<nb_edge, B>>>(src, dst, E);
    k_mid       <<<nb_node32, B>>>(W1, b1, W2, n);
    k_scatter<2><<<nb_edge, B>>>(src, dst, E);
    k_post      <<<nb_node4, B>>>(b2, out, n);
}